// round 2
// baseline (speedup 1.0000x reference)
#include <cuda_runtime.h>
#include <math.h>
#include <string.h>

#define BB 64
#define TT 256
#define DD 512
#define HH 1024
#define G4 4096
#define OO 512
#define NBLK 128
#define NTHR 256

// ---------------- scratch (device globals: allocation-free rule) -----------
__device__ float g_seq1[(size_t)TT * BB * HH];   // 64 MB, [t][b][h]
__device__ float g_hA[BB * HH];
__device__ float g_hB[BB * HH];
__device__ unsigned g_count = 0;
__device__ volatile unsigned g_gen = 0;

// ---------------- packed fp32x2 FMA (sm_103a FFMA2 path) -------------------
#define FMA2(d, a, b) \
    asm("fma.rn.f32x2 %0, %1, %2, %0;" : "+l"(d) : "l"(a), "l"(b))

union F4U { float4 f; unsigned long long u[2]; };

__device__ __forceinline__ unsigned long long f2_ull(float2 v) {
    unsigned long long r; memcpy(&r, &v, 8); return r;
}
__device__ __forceinline__ void unpack2(unsigned long long v, float& lo, float& hi) {
    unsigned a, b;
    asm("mov.b64 {%0, %1}, %2;" : "=r"(a), "=r"(b) : "l"(v));
    lo = __uint_as_float(a); hi = __uint_as_float(b);
}

// ---------------- software grid barrier (all NBLK blocks resident) ---------
__device__ __forceinline__ void grid_barrier() {
    __syncthreads();
    if (threadIdx.x == 0) {
        __threadfence();                       // make my h-writes visible
        unsigned gen = g_gen;
        if (atomicAdd(&g_count, 1u) == NBLK - 1u) {
            g_count = 0u;
            __threadfence();
            g_gen = gen + 1u;                  // release
        } else {
            while (g_gen == gen) __nanosleep(40);
        }
        __threadfence();
    }
    __syncthreads();
}

// ---------------------------------------------------------------------------
// Persistent LSTM layer.
//   Each block owns 8 hidden units (u0..u0+7) => 32 weight columns
//   (4 gates x 8 units). Per step:  z = x_t @ W + h @ U  (K = kx + 1024),
//   then gate math, c kept in registers, h ping-pong through global.
//   A-tiles (h, x_t) read with __ldcg (L2-coherent, keeps L1 for weights).
// ---------------------------------------------------------------------------
template<bool WRITE_SEQ>
__global__ __launch_bounds__(NTHR) void lstm_layer(
    const float* __restrict__ xbase, size_t xrow, size_t xstep, int kx,
    const float* __restrict__ W,    // [kx][4096]
    const float* __restrict__ U,    // [1024][4096]
    const float* __restrict__ bias, // [4096]
    float* __restrict__ seq_out)    // [T][B][H] or null
{
    __shared__ float As[16][66];   // A^T chunk  (conflict-free: 66 pad)
    __shared__ float Bsd[16][64];  // weight chunk, every value DUPLICATED
    __shared__ float zs[64][36];   // z staging for gate fusion

    const int tid = threadIdx.x;
    const int u0  = blockIdx.x * 8;
    const int tx  = tid & 7;          // 4 cols:  tx*4 .. tx*4+3
    const int ty2 = (tid >> 3) * 2;   // 2 rows:  ty2, ty2+1

    // A-tile load mapping: 64 rows x 16 k, float4 per thread
    const int a_row = tid >> 2;
    const int a_k4  = (tid & 3) * 4;
    // B-tile load mapping: 16 k-rows x 32 cols, float2 per thread
    const int b_k  = tid >> 4;
    const int c2   = (tid & 15) * 2;            // col pair base (even)
    const int wcol = (c2 >> 3) * HH + u0 + (c2 & 7); // global weight column
    const int bsd_off = ((c2 & 3) == 0) ? ((c2 >> 2) * 4) : (32 + (c2 >> 2) * 4);

    // ---- init: zero my h slice, c in registers, preload bias -------------
    float creg[2] = {0.f, 0.f};
    float bgs[2][4];
#pragma unroll
    for (int i = 0; i < 2; i++) {
        int p = tid + i * 256;          // pair: b = p>>3, uu = p&7
        int b = p >> 3, uu = p & 7;
        g_hA[b * HH + u0 + uu] = 0.f;
#pragma unroll
        for (int g = 0; g < 4; g++)
            bgs[i][g] = __ldg(&bias[g * HH + u0 + uu]);
    }
    grid_barrier();

    for (int t = 0; t < TT; t++) {
        const float* hp = (t & 1) ? g_hB : g_hA;
        float*       hn = (t & 1) ? g_hA : g_hB;
        const float* xt = xbase + (size_t)t * xstep;

        unsigned long long acc0 = 0ull, acc1 = 0ull, acc2 = 0ull, acc3 = 0ull;

#define GEMM_PHASE(APTR, ASTRIDE, WPTR, KLEN)                                   \
        for (int k0 = 0; k0 < (KLEN); k0 += 16) {                               \
            float4 av = __ldcg((const float4*)((APTR) +                         \
                               (size_t)a_row * (ASTRIDE) + k0 + a_k4));         \
            float2 bv = *(const float2*)((WPTR) +                               \
                               (size_t)(k0 + b_k) * G4 + wcol);                 \
            __syncthreads();                                                    \
            As[a_k4 + 0][a_row] = av.x;                                         \
            As[a_k4 + 1][a_row] = av.y;                                         \
            As[a_k4 + 2][a_row] = av.z;                                         \
            As[a_k4 + 3][a_row] = av.w;                                         \
            *(float4*)&Bsd[b_k][bsd_off] = make_float4(bv.x, bv.x, bv.y, bv.y); \
            __syncthreads();                                                    \
            _Pragma("unroll")                                                   \
            for (int kk = 0; kk < 16; kk++) {                                   \
                unsigned long long a2 = f2_ull(*(const float2*)&As[kk][ty2]);   \
                F4U b0; b0.f = *(const float4*)&Bsd[kk][tx * 4];                \
                F4U b1; b1.f = *(const float4*)&Bsd[kk][32 + tx * 4];           \
                FMA2(acc0, a2, b0.u[0]);                                        \
                FMA2(acc1, a2, b0.u[1]);                                        \
                FMA2(acc2, a2, b1.u[0]);                                        \
                FMA2(acc3, a2, b1.u[1]);                                        \
            }                                                                   \
        }

        GEMM_PHASE(hp, HH, U, HH)       // recurrent part
        GEMM_PHASE(xt, xrow, W, kx)     // input part (fused)
#undef GEMM_PHASE

        // ---- epilogue: stage z into smem ---------------------------------
        {
            float r0[4], r1[4];
            unpack2(acc0, r0[0], r1[0]);
            unpack2(acc1, r0[1], r1[1]);
            unpack2(acc2, r0[2], r1[2]);
            unpack2(acc3, r0[3], r1[3]);
            *(float4*)&zs[ty2][tx * 4]     = make_float4(r0[0], r0[1], r0[2], r0[3]);
            *(float4*)&zs[ty2 + 1][tx * 4] = make_float4(r1[0], r1[1], r1[2], r1[3]);
        }
        __syncthreads();

        // ---- gates: 2 (b,unit) pairs per thread --------------------------
#pragma unroll
        for (int i = 0; i < 2; i++) {
            int p = tid + i * 256;
            int b = p >> 3, uu = p & 7;
            float zi = zs[b][0 * 8 + uu] + bgs[i][0];
            float zf = zs[b][1 * 8 + uu] + bgs[i][1];
            float zg = zs[b][2 * 8 + uu] + bgs[i][2];
            float zo = zs[b][3 * 8 + uu] + bgs[i][3];
            float ig = 1.f / (1.f + expf(-zi));
            float fg = 1.f / (1.f + expf(-zf));
            float og = 1.f / (1.f + expf(-zo));
            float cn = fg * creg[i] + ig * tanhf(zg);
            float hv = og * tanhf(cn);
            creg[i] = cn;
            hn[b * HH + u0 + uu] = hv;
            if (WRITE_SEQ)
                seq_out[((size_t)t * BB + b) * HH + u0 + uu] = hv;
        }
        grid_barrier();   // h fully written before anyone reads next step
    }
}

// ---------------------------------------------------------------------------
// Final dense: out[b][o] = h_final[b][:] . Wd[:,o] + bd[o]   (h_final = g_hA,
// since T=256 is even: step 255 writes into g_hA)
// ---------------------------------------------------------------------------
__global__ __launch_bounds__(OO) void dense_kernel(
    const float* __restrict__ Wd, const float* __restrict__ bd,
    float* __restrict__ out)
{
    __shared__ float hs[HH];
    int b = blockIdx.x;
    int o = threadIdx.x;
    for (int k = o; k < HH; k += OO) hs[k] = g_hA[(size_t)b * HH + k];
    __syncthreads();
    float acc = 0.f;
#pragma unroll 8
    for (int k = 0; k < HH; k++)
        acc += hs[k] * __ldg(&Wd[(size_t)k * OO + o]);
    out[(size_t)b * OO + o] = acc + bd[o];
}

// ---------------------------------------------------------------------------
extern "C" void kernel_launch(void* const* d_in, const int* in_sizes, int n_in,
                              void* d_out, int out_size)
{
    const float* x  = (const float*)d_in[0];
    const float* W1 = (const float*)d_in[1];
    const float* U1 = (const float*)d_in[2];
    const float* b1 = (const float*)d_in[3];
    const float* W2 = (const float*)d_in[4];
    const float* U2 = (const float*)d_in[5];
    const float* b2 = (const float*)d_in[6];
    const float* Wd = (const float*)d_in[7];
    const float* bd = (const float*)d_in[8];
    float* out = (float*)d_out;

    float* seq1;
    cudaGetSymbolAddress((void**)&seq1, g_seq1);

    // Layer 1: x [B,T,D] row stride T*D, step stride D; writes seq1 [t][b][h]
    lstm_layer<true><<<NBLK, NTHR>>>(
        x, (size_t)TT * DD, (size_t)DD, DD, W1, U1, b1, seq1);

    // Layer 2: seq1 [t][b][h] row stride H, step stride B*H; no seq output
    lstm_layer<false><<<NBLK, NTHR>>>(
        seq1, (size_t)HH, (size_t)BB * HH, HH, W2, U2, b2, nullptr);

    // Dense head on final h (in g_hA)
    dense_kernel<<<BB, OO>>>(Wd, bd, out);
}

// round 4
// speedup vs baseline: 2.9157x; 2.9157x over previous
#include <cuda_runtime.h>
#include <mma.h>
#include <math.h>

using namespace nvcuda;

#define BB 64
#define TT 256
#define DD 512
#define HH 1024
#define G4 4096
#define OO 512
#define NBLK 128
#define NTHR 256
#define MROWS (BB*TT)   // 16384

// ---------------- scratch (device globals: allocation-free rule) -----------
__device__ float g_xz[(size_t)MROWS * G4];     // 256 MB
__device__ float g_seq1[(size_t)MROWS * HH];   // 64 MB, [t][b][h]
__device__ float g_Wt[(size_t)HH * G4];        // tf32-truncated W
__device__ float g_Ut[(size_t)HH * G4];        // tf32-truncated U
__device__ float g_hA[BB * HH];
__device__ float g_hB[BB * HH];
__device__ unsigned g_count = 0;
__device__ volatile unsigned g_gen = 0;

__device__ __forceinline__ float to_tf32(float x) {
    float r; asm("cvt.rna.tf32.f32 %0, %1;" : "=f"(r) : "f"(x)); return r;
}

// ---------------- software grid barrier (all NBLK blocks resident) ---------
__device__ __forceinline__ void grid_barrier() {
    __syncthreads();
    if (threadIdx.x == 0) {
        __threadfence();
        unsigned gen = g_gen;
        if (atomicAdd(&g_count, 1u) == NBLK - 1u) {
            g_count = 0u;
            __threadfence();
            g_gen = gen + 1u;
        } else {
            while (g_gen == gen) __nanosleep(40);
        }
        __threadfence();
    }
    __syncthreads();
}

// ---------------- tf32 pre-truncation of weights ---------------------------
__global__ void trunc_kernel(const float* __restrict__ in,
                             float* __restrict__ out, int n4)
{
    int i = blockIdx.x * blockDim.x + threadIdx.x;
    if (i < n4) {
        float4 v = ((const float4*)in)[i];
        v.x = to_tf32(v.x); v.y = to_tf32(v.y);
        v.z = to_tf32(v.z); v.w = to_tf32(v.w);
        ((float4*)out)[i] = v;
    }
}

// ---------------------------------------------------------------------------
// Input GEMM (parallel over all timesteps): C[r][n] = A[r][:] @ Bt[:][n]
// Block tile 128x64, 8 warps, warp tile 32x32 (2x2 m16n16k8 tf32 frags).
// REMAP=1: A row for output row r=(t*64+b) is x row (b*256+t).
// ---------------------------------------------------------------------------
template<int REMAP>
__global__ __launch_bounds__(256) void input_gemm(
    const float* __restrict__ A, const float* __restrict__ Bt,
    float* __restrict__ C, int K)
{
    __shared__ __align__(32) float As[128][48];
    __shared__ __align__(32) float Bs[32][72];
    const int tid = threadIdx.x;
    const int wid = tid >> 5;
    const int wm = wid >> 1, wn = wid & 1;
    const int r0 = blockIdx.y * 128, n0 = blockIdx.x * 64;

    wmma::fragment<wmma::accumulator, 16, 16, 8, float> c[2][2];
#pragma unroll
    for (int i = 0; i < 2; i++)
#pragma unroll
        for (int j = 0; j < 2; j++) wmma::fill_fragment(c[i][j], 0.f);

    const int arow = tid >> 1, ak0 = (tid & 1) * 16;
    const int rr = r0 + arow;
    const size_t gr = REMAP ? ((size_t)(rr & 63) * TT + (rr >> 6)) : (size_t)rr;
    const float* aptr = A + gr * K + ak0;
    const int bkr = tid >> 3, bc0 = (tid & 7) * 8;
    const float* bptr = Bt + (size_t)bkr * G4 + n0 + bc0;

    for (int kc = 0; kc < K; kc += 32) {
        float4 av[4], bv[2];
#pragma unroll
        for (int i = 0; i < 4; i++)
            av[i] = *((const float4*)(aptr + kc) + i);
#pragma unroll
        for (int i = 0; i < 2; i++)
            bv[i] = *((const float4*)(bptr + (size_t)kc * G4) + i);
        __syncthreads();
#pragma unroll
        for (int i = 0; i < 4; i++) {
            As[arow][ak0 + i * 4 + 0] = to_tf32(av[i].x);
            As[arow][ak0 + i * 4 + 1] = to_tf32(av[i].y);
            As[arow][ak0 + i * 4 + 2] = to_tf32(av[i].z);
            As[arow][ak0 + i * 4 + 3] = to_tf32(av[i].w);
        }
        *(float4*)&Bs[bkr][bc0]     = bv[0];
        *(float4*)&Bs[bkr][bc0 + 4] = bv[1];
        __syncthreads();
#pragma unroll
        for (int kk = 0; kk < 4; kk++) {
            wmma::fragment<wmma::matrix_a, 16, 16, 8, wmma::precision::tf32, wmma::row_major> a[2];
            wmma::fragment<wmma::matrix_b, 16, 16, 8, wmma::precision::tf32, wmma::row_major> b[2];
#pragma unroll
            for (int i = 0; i < 2; i++)
                wmma::load_matrix_sync(a[i], &As[wm * 32 + i * 16][kk * 8], 48);
#pragma unroll
            for (int j = 0; j < 2; j++)
                wmma::load_matrix_sync(b[j], &Bs[kk * 8][wn * 32 + j * 16], 72);
#pragma unroll
            for (int i = 0; i < 2; i++)
#pragma unroll
                for (int j = 0; j < 2; j++)
                    wmma::mma_sync(c[i][j], a[i], b[j], c[i][j]);
        }
    }
#pragma unroll
    for (int i = 0; i < 2; i++)
#pragma unroll
        for (int j = 0; j < 2; j++)
            wmma::store_matrix_sync(
                C + (size_t)(r0 + wm * 32 + i * 16) * G4 + n0 + wn * 32 + j * 16,
                c[i][j], G4, wmma::mem_row_major);
}

// ---------------------------------------------------------------------------
// Persistent recurrent layer. Block owns 8 hidden units (u0..u0+7) =>
// 32 gate columns. Per step: z_rec = h @ U via tf32 WMMA
// (warps: 4 m-tiles x 2 k-splits), fused gates, c in registers,
// h ping-pong via global + grid barrier.
// smem: As 64x68 (17408) + Bs 64x36 (9216) + zs 2x64x40 (20480) = 47104 B
// ---------------------------------------------------------------------------
template<bool WRITE_SEQ>
__global__ __launch_bounds__(NTHR) void lstm_rec(
    const float* __restrict__ xz,   // [t*64+b][4096]
    const float* __restrict__ U,    // [1024][4096] tf32-truncated
    const float* __restrict__ bias, // [4096]
    float* __restrict__ seq_out)    // [t*64+b][1024] or null
{
    __shared__ __align__(32) float As[64][68];
    __shared__ __align__(32) float Bs[64][36];
    __shared__ __align__(32) float zs[2][64][40];

    const int tid = threadIdx.x;
    const int wid = tid >> 5;
    const int wm = wid & 3;    // m-tile 0..3
    const int ks = wid >> 2;   // k-split 0..1
    const int u0 = blockIdx.x * 8;

    float creg[2] = {0.f, 0.f};
    float bgs[2][4];
#pragma unroll
    for (int i = 0; i < 2; i++) {
        int p = tid + i * 256;
        int b = p >> 3, uu = p & 7;
        g_hA[b * HH + u0 + uu] = 0.f;
#pragma unroll
        for (int g = 0; g < 4; g++)
            bgs[i][g] = __ldg(&bias[g * HH + u0 + uu]);
    }
    grid_barrier();

    const int arow = tid >> 2, ak0 = (tid & 3) * 16;   // 64 rows x 64 k
    const int bkr = tid >> 2, bg = tid & 3;            // 64 k-rows x 4 gates

    for (int t = 0; t < TT; t++) {
        const float* hp = (t & 1) ? g_hB : g_hA;
        float*       hn = (t & 1) ? g_hA : g_hB;

        wmma::fragment<wmma::accumulator, 16, 16, 8, float> c[2];
        wmma::fill_fragment(c[0], 0.f);
        wmma::fill_fragment(c[1], 0.f);

        for (int kc = 0; kc < HH; kc += 64) {
            float4 av[4], bv[2];
#pragma unroll
            for (int i = 0; i < 4; i++)
                av[i] = __ldcg((const float4*)(hp + (size_t)arow * HH + kc + ak0) + i);
            const float* bp = U + (size_t)(kc + bkr) * G4 + bg * HH + u0;
            bv[0] = *(const float4*)bp;
            bv[1] = *((const float4*)bp + 1);
            __syncthreads();
#pragma unroll
            for (int i = 0; i < 4; i++) {
                As[arow][ak0 + i * 4 + 0] = to_tf32(av[i].x);
                As[arow][ak0 + i * 4 + 1] = to_tf32(av[i].y);
                As[arow][ak0 + i * 4 + 2] = to_tf32(av[i].z);
                As[arow][ak0 + i * 4 + 3] = to_tf32(av[i].w);
            }
            *(float4*)&Bs[bkr][bg * 8]     = bv[0];
            *(float4*)&Bs[bkr][bg * 8 + 4] = bv[1];
            __syncthreads();
#pragma unroll
            for (int j = 0; j < 4; j++) {
                int kk = ks * 4 + j;
                wmma::fragment<wmma::matrix_a, 16, 16, 8, wmma::precision::tf32, wmma::row_major> a;
                wmma::fragment<wmma::matrix_b, 16, 16, 8, wmma::precision::tf32, wmma::row_major> b0, b1;
                wmma::load_matrix_sync(a, &As[wm * 16][kk * 8], 68);
                wmma::load_matrix_sync(b0, &Bs[kk * 8][0], 36);
                wmma::load_matrix_sync(b1, &Bs[kk * 8][16], 36);
                wmma::mma_sync(c[0], a, b0, c[0]);
                wmma::mma_sync(c[1], a, b1, c[1]);
            }
        }
        wmma::store_matrix_sync(&zs[ks][wm * 16][0],  c[0], 40, wmma::mem_row_major);
        wmma::store_matrix_sync(&zs[ks][wm * 16][16], c[1], 40, wmma::mem_row_major);
        __syncthreads();

        // ---- fused gates -------------------------------------------------
#pragma unroll
        for (int i = 0; i < 2; i++) {
            int p = tid + i * 256;
            int b = p >> 3, uu = p & 7;
            const float* xzr = xz + ((size_t)t * BB + b) * G4;
            float zi = zs[0][b][0 * 8 + uu] + zs[1][b][0 * 8 + uu] + xzr[0 * HH + u0 + uu] + bgs[i][0];
            float zf = zs[0][b][1 * 8 + uu] + zs[1][b][1 * 8 + uu] + xzr[1 * HH + u0 + uu] + bgs[i][1];
            float zg = zs[0][b][2 * 8 + uu] + zs[1][b][2 * 8 + uu] + xzr[2 * HH + u0 + uu] + bgs[i][2];
            float zo = zs[0][b][3 * 8 + uu] + zs[1][b][3 * 8 + uu] + xzr[3 * HH + u0 + uu] + bgs[i][3];
            float ig = 1.f / (1.f + expf(-zi));
            float fg = 1.f / (1.f + expf(-zf));
            float og = 1.f / (1.f + expf(-zo));
            float cn = fg * creg[i] + ig * tanhf(zg);
            float hv = og * tanhf(cn);
            creg[i] = cn;
            hn[b * HH + u0 + uu] = hv;
            if (WRITE_SEQ)
                seq_out[((size_t)t * BB + b) * HH + u0 + uu] = hv;
        }
        grid_barrier();
    }
}

// ---------------------------------------------------------------------------
// Final dense: out[b][o] = h_final[b][:] . Wd[:,o] + bd[o]  (h_final = g_hA)
// ---------------------------------------------------------------------------
__global__ __launch_bounds__(OO) void dense_kernel(
    const float* __restrict__ Wd, const float* __restrict__ bd,
    float* __restrict__ out)
{
    __shared__ float hs[HH];
    int b = blockIdx.x;
    int o = threadIdx.x;
    for (int k = o; k < HH; k += OO) hs[k] = g_hA[(size_t)b * HH + k];
    __syncthreads();
    float acc = 0.f;
#pragma unroll 8
    for (int k = 0; k < HH; k++)
        acc += hs[k] * __ldg(&Wd[(size_t)k * OO + o]);
    out[(size_t)b * OO + o] = acc + bd[o];
}

// ---------------------------------------------------------------------------
extern "C" void kernel_launch(void* const* d_in, const int* in_sizes, int n_in,
                              void* d_out, int out_size)
{
    const float* x  = (const float*)d_in[0];
    const float* W1 = (const float*)d_in[1];
    const float* U1 = (const float*)d_in[2];
    const float* b1 = (const float*)d_in[3];
    const float* W2 = (const float*)d_in[4];
    const float* U2 = (const float*)d_in[5];
    const float* b2 = (const float*)d_in[6];
    const float* Wd = (const float*)d_in[7];
    const float* bd = (const float*)d_in[8];
    float* out = (float*)d_out;

    float *xz, *seq1, *Wt, *Ut;
    cudaGetSymbolAddress((void**)&xz,   g_xz);
    cudaGetSymbolAddress((void**)&seq1, g_seq1);
    cudaGetSymbolAddress((void**)&Wt,   g_Wt);
    cudaGetSymbolAddress((void**)&Ut,   g_Ut);

    // ---- layer 1 ----
    trunc_kernel<<<(DD * G4 / 4 + 255) / 256, 256>>>(W1, Wt, DD * G4 / 4);
    input_gemm<1><<<dim3(G4 / 64, MROWS / 128), 256>>>(x, Wt, xz, DD);
    trunc_kernel<<<(HH * G4 / 4 + 255) / 256, 256>>>(U1, Ut, HH * G4 / 4);
    lstm_rec<true><<<NBLK, NTHR>>>(xz, Ut, b1, seq1);

    // ---- layer 2 ----
    trunc_kernel<<<(HH * G4 / 4 + 255) / 256, 256>>>(W2, Wt, HH * G4 / 4);
    input_gemm<0><<<dim3(G4 / 64, MROWS / 128), 256>>>(seq1, Wt, xz, HH);
    trunc_kernel<<<(HH * G4 / 4 + 255) / 256, 256>>>(U2, Ut, HH * G4 / 4);
    lstm_rec<false><<<NBLK, NTHR>>>(xz, Ut, b2, nullptr);

    // ---- dense head ----
    dense_kernel<<<BB, OO>>>(Wd, bd, out);
}

// round 6
// speedup vs baseline: 3.0861x; 1.0584x over previous
#include <cuda_runtime.h>
#include <mma.h>
#include <math.h>

using namespace nvcuda;

#define BB 64
#define TT 256
#define DD 512
#define HH 1024
#define G4 4096
#define OO 512
#define NBLK 128
#define NTHR 256
#define MROWS (BB*TT)   // 16384

// ---------------- scratch (device globals: allocation-free rule) -----------
__device__ float g_xz[(size_t)MROWS * G4];     // 256 MB
__device__ float g_seq1[(size_t)MROWS * HH];   // 64 MB, [t][b][h]
__device__ float g_Wt[(size_t)HH * G4];        // tf32-truncated W
__device__ float g_Ut[(size_t)HH * G4];        // tf32-truncated U
__device__ float g_hA[BB * HH];
__device__ float g_hB[BB * HH];
__device__ unsigned g_count = 0;
__device__ volatile unsigned g_gen = 0;

__device__ __forceinline__ float to_tf32(float x) {
    float r; asm("cvt.rna.tf32.f32 %0, %1;" : "=f"(r) : "f"(x)); return r;
}

// ---------------- software grid barrier (all NBLK blocks resident) ---------
__device__ __forceinline__ void grid_barrier() {
    __syncthreads();
    if (threadIdx.x == 0) {
        __threadfence();
        unsigned gen = g_gen;
        if (atomicAdd(&g_count, 1u) == NBLK - 1u) {
            g_count = 0u;
            __threadfence();
            g_gen = gen + 1u;
        } else {
            while (g_gen == gen) __nanosleep(40);
        }
        __threadfence();
    }
    __syncthreads();
}

// ---------------- tf32 pre-truncation of weights ---------------------------
__global__ void trunc_kernel(const float* __restrict__ in,
                             float* __restrict__ out, int n4)
{
    int i = blockIdx.x * blockDim.x + threadIdx.x;
    if (i < n4) {
        float4 v = ((const float4*)in)[i];
        v.x = to_tf32(v.x); v.y = to_tf32(v.y);
        v.z = to_tf32(v.z); v.w = to_tf32(v.w);
        ((float4*)out)[i] = v;
    }
}

// ---------------------------------------------------------------------------
// Input GEMM v2: C[r][n] = A[r][:] @ Bt[:][n]
// Block tile 128x128, BK=16, double-buffered smem, 8 warps (2x4),
// warp tile 64x32 = 4x2 m16n16k8 tf32 frags.
// REMAP=1: A row for output row r=(t*64+b) is x row (b*256+t).
// smem: As 2*128*20*4 = 20480 + Bs 2*16*136*4 = 17408 -> 37888 B
// ---------------------------------------------------------------------------
template<int REMAP>
__global__ __launch_bounds__(256) void input_gemm(
    const float* __restrict__ A, const float* __restrict__ Bt,
    float* __restrict__ C, int K)
{
    __shared__ __align__(16) float As[2][128][20];
    __shared__ __align__(16) float Bs[2][16][136];
    const int tid = threadIdx.x;
    const int wid = tid >> 5;
    const int wr = wid >> 2;        // 0..1  (row block of 64)
    const int wc = wid & 3;         // 0..3  (col block of 32)
    const int r0 = blockIdx.y * 128, n0 = blockIdx.x * 128;

    wmma::fragment<wmma::accumulator, 16, 16, 8, float> c[4][2];
#pragma unroll
    for (int i = 0; i < 4; i++)
#pragma unroll
        for (int j = 0; j < 2; j++) wmma::fill_fragment(c[i][j], 0.f);

    // A staging: 128 rows x 16 k, 8 floats per thread
    const int arow = tid >> 1, ac8 = (tid & 1) * 8;
    const int rr = r0 + arow;
    const size_t gr = REMAP ? ((size_t)(rr & 63) * TT + (rr >> 6)) : (size_t)rr;
    const float* aptr = A + gr * K + ac8;
    // B staging: 16 k-rows x 128 cols, 8 floats per thread
    const int brow = tid >> 4, bc8 = (tid & 15) * 8;
    const float* bptr = Bt + (size_t)brow * G4 + n0 + bc8;

    float4 a0, a1, b0, b1;

#define LOADK(kc)                                                   \
    do {                                                            \
        a0 = *(const float4*)(aptr + (kc));                         \
        a1 = *(const float4*)(aptr + (kc) + 4);                     \
        b0 = *(const float4*)(bptr + (size_t)(kc) * G4);            \
        b1 = *(const float4*)(bptr + (size_t)(kc) * G4 + 4);        \
    } while (0)

#define STOREK(s)                                                   \
    do {                                                            \
        As[s][arow][ac8 + 0] = to_tf32(a0.x);                       \
        As[s][arow][ac8 + 1] = to_tf32(a0.y);                       \
        As[s][arow][ac8 + 2] = to_tf32(a0.z);                       \
        As[s][arow][ac8 + 3] = to_tf32(a0.w);                       \
        As[s][arow][ac8 + 4] = to_tf32(a1.x);                       \
        As[s][arow][ac8 + 5] = to_tf32(a1.y);                       \
        As[s][arow][ac8 + 6] = to_tf32(a1.z);                       \
        As[s][arow][ac8 + 7] = to_tf32(a1.w);                       \
        *(float4*)&Bs[s][brow][bc8]     = b0;                       \
        *(float4*)&Bs[s][brow][bc8 + 4] = b1;                       \
    } while (0)

    LOADK(0);
    STOREK(0);
    __syncthreads();

    int s = 0;
    for (int kc = 0; kc < K; kc += 16) {
        const int nxt = kc + 16;
        if (nxt < K) LOADK(nxt);
#pragma unroll
        for (int kk = 0; kk < 2; kk++) {
            wmma::fragment<wmma::matrix_a, 16, 16, 8, wmma::precision::tf32, wmma::row_major> af[4];
            wmma::fragment<wmma::matrix_b, 16, 16, 8, wmma::precision::tf32, wmma::row_major> bf[2];
#pragma unroll
            for (int i = 0; i < 4; i++)
                wmma::load_matrix_sync(af[i], &As[s][wr * 64 + i * 16][kk * 8], 20);
#pragma unroll
            for (int j = 0; j < 2; j++)
                wmma::load_matrix_sync(bf[j], &Bs[s][kk * 8][wc * 32 + j * 16], 136);
#pragma unroll
            for (int i = 0; i < 4; i++)
#pragma unroll
                for (int j = 0; j < 2; j++)
                    wmma::mma_sync(c[i][j], af[i], bf[j], c[i][j]);
        }
        if (nxt < K) STOREK(s ^ 1);
        s ^= 1;
        __syncthreads();
    }
#undef LOADK
#undef STOREK

#pragma unroll
    for (int i = 0; i < 4; i++)
#pragma unroll
        for (int j = 0; j < 2; j++)
            wmma::store_matrix_sync(
                C + (size_t)(r0 + wr * 64 + i * 16) * G4 + n0 + wc * 32 + j * 16,
                c[i][j], G4, wmma::mem_row_major);
}

// ---------------------------------------------------------------------------
// Persistent recurrent layer (unchanged from round 4 — known good).
// ---------------------------------------------------------------------------
template<bool WRITE_SEQ>
__global__ __launch_bounds__(NTHR) void lstm_rec(
    const float* __restrict__ xz,   // [t*64+b][4096]
    const float* __restrict__ U,    // [1024][4096] tf32-truncated
    const float* __restrict__ bias, // [4096]
    float* __restrict__ seq_out)    // [t*64+b][1024] or null
{
    __shared__ __align__(32) float As[64][68];
    __shared__ __align__(32) float Bs[64][36];
    __shared__ __align__(32) float zs[2][64][40];

    const int tid = threadIdx.x;
    const int wid = tid >> 5;
    const int wm = wid & 3;    // m-tile 0..3
    const int ks = wid >> 2;   // k-split 0..1
    const int u0 = blockIdx.x * 8;

    float creg[2] = {0.f, 0.f};
    float bgs[2][4];
#pragma unroll
    for (int i = 0; i < 2; i++) {
        int p = tid + i * 256;
        int b = p >> 3, uu = p & 7;
        g_hA[b * HH + u0 + uu] = 0.f;
#pragma unroll
        for (int g = 0; g < 4; g++)
            bgs[i][g] = __ldg(&bias[g * HH + u0 + uu]);
    }
    grid_barrier();

    const int arow = tid >> 2, ak0 = (tid & 3) * 16;   // 64 rows x 64 k
    const int bkr = tid >> 2, bg = tid & 3;            // 64 k-rows x 4 gates

    for (int t = 0; t < TT; t++) {
        const float* hp = (t & 1) ? g_hB : g_hA;
        float*       hn = (t & 1) ? g_hA : g_hB;

        wmma::fragment<wmma::accumulator, 16, 16, 8, float> c[2];
        wmma::fill_fragment(c[0], 0.f);
        wmma::fill_fragment(c[1], 0.f);

        for (int kc = 0; kc < HH; kc += 64) {
            float4 av[4], bv[2];
#pragma unroll
            for (int i = 0; i < 4; i++)
                av[i] = __ldcg((const float4*)(hp + (size_t)arow * HH + kc + ak0) + i);
            const float* bp = U + (size_t)(kc + bkr) * G4 + bg * HH + u0;
            bv[0] = *(const float4*)bp;
            bv[1] = *((const float4*)bp + 1);
            __syncthreads();
#pragma unroll
            for (int i = 0; i < 4; i++) {
                As[arow][ak0 + i * 4 + 0] = to_tf32(av[i].x);
                As[arow][ak0 + i * 4 + 1] = to_tf32(av[i].y);
                As[arow][ak0 + i * 4 + 2] = to_tf32(av[i].z);
                As[arow][ak0 + i * 4 + 3] = to_tf32(av[i].w);
            }
            *(float4*)&Bs[bkr][bg * 8]     = bv[0];
            *(float4*)&Bs[bkr][bg * 8 + 4] = bv[1];
            __syncthreads();
#pragma unroll
            for (int j = 0; j < 4; j++) {
                int kk = ks * 4 + j;
                wmma::fragment<wmma::matrix_a, 16, 16, 8, wmma::precision::tf32, wmma::row_major> a;
                wmma::fragment<wmma::matrix_b, 16, 16, 8, wmma::precision::tf32, wmma::row_major> b0, b1;
                wmma::load_matrix_sync(a, &As[wm * 16][kk * 8], 68);
                wmma::load_matrix_sync(b0, &Bs[kk * 8][0], 36);
                wmma::load_matrix_sync(b1, &Bs[kk * 8][16], 36);
                wmma::mma_sync(c[0], a, b0, c[0]);
                wmma::mma_sync(c[1], a, b1, c[1]);
            }
        }
        wmma::store_matrix_sync(&zs[ks][wm * 16][0],  c[0], 40, wmma::mem_row_major);
        wmma::store_matrix_sync(&zs[ks][wm * 16][16], c[1], 40, wmma::mem_row_major);
        __syncthreads();

        // ---- fused gates -------------------------------------------------
#pragma unroll
        for (int i = 0; i < 2; i++) {
            int p = tid + i * 256;
            int b = p >> 3, uu = p & 7;
            const float* xzr = xz + ((size_t)t * BB + b) * G4;
            float zi = zs[0][b][0 * 8 + uu] + zs[1][b][0 * 8 + uu] + xzr[0 * HH + u0 + uu] + bgs[i][0];
            float zf = zs[0][b][1 * 8 + uu] + zs[1][b][1 * 8 + uu] + xzr[1 * HH + u0 + uu] + bgs[i][1];
            float zg = zs[0][b][2 * 8 + uu] + zs[1][b][2 * 8 + uu] + xzr[2 * HH + u0 + uu] + bgs[i][2];
            float zo = zs[0][b][3 * 8 + uu] + zs[1][b][3 * 8 + uu] + xzr[3 * HH + u0 + uu] + bgs[i][3];
            float ig = 1.f / (1.f + expf(-zi));
            float fg = 1.f / (1.f + expf(-zf));
            float og = 1.f / (1.f + expf(-zo));
            float cn = fg * creg[i] + ig * tanhf(zg);
            float hv = og * tanhf(cn);
            creg[i] = cn;
            hn[b * HH + u0 + uu] = hv;
            if (WRITE_SEQ)
                seq_out[((size_t)t * BB + b) * HH + u0 + uu] = hv;
        }
        grid_barrier();
    }
}

// ---------------------------------------------------------------------------
// Final dense: out[b][o] = h_final[b][:] . Wd[:,o] + bd[o]  (h_final = g_hA)
// ---------------------------------------------------------------------------
__global__ __launch_bounds__(OO) void dense_kernel(
    const float* __restrict__ Wd, const float* __restrict__ bd,
    float* __restrict__ out)
{
    __shared__ float hs[HH];
    int b = blockIdx.x;
    int o = threadIdx.x;
    for (int k = o; k < HH; k += OO) hs[k] = g_hA[(size_t)b * HH + k];
    __syncthreads();
    float acc = 0.f;
#pragma unroll 8
    for (int k = 0; k < HH; k++)
        acc += hs[k] * __ldg(&Wd[(size_t)k * OO + o]);
    out[(size_t)b * OO + o] = acc + bd[o];
}

// ---------------------------------------------------------------------------
extern "C" void kernel_launch(void* const* d_in, const int* in_sizes, int n_in,
                              void* d_out, int out_size)
{
    const float* x  = (const float*)d_in[0];
    const float* W1 = (const float*)d_in[1];
    const float* U1 = (const float*)d_in[2];
    const float* b1 = (const float*)d_in[3];
    const float* W2 = (const float*)d_in[4];
    const float* U2 = (const float*)d_in[5];
    const float* b2 = (const float*)d_in[6];
    const float* Wd = (const float*)d_in[7];
    const float* bd = (const float*)d_in[8];
    float* out = (float*)d_out;

    float *xz, *seq1, *Wt, *Ut;
    cudaGetSymbolAddress((void**)&xz,   g_xz);
    cudaGetSymbolAddress((void**)&seq1, g_seq1);
    cudaGetSymbolAddress((void**)&Wt,   g_Wt);
    cudaGetSymbolAddress((void**)&Ut,   g_Ut);

    // ---- layer 1 ----
    trunc_kernel<<<(DD * G4 / 4 + 255) / 256, 256>>>(W1, Wt, DD * G4 / 4);
    input_gemm<1><<<dim3(G4 / 128, MROWS / 128), 256>>>(x, Wt, xz, DD);
    trunc_kernel<<<(HH * G4 / 4 + 255) / 256, 256>>>(U1, Ut, HH * G4 / 4);
    lstm_rec<true><<<NBLK, NTHR>>>(xz, Ut, b1, seq1);

    // ---- layer 2 ----
    trunc_kernel<<<(HH * G4 / 4 + 255) / 256, 256>>>(W2, Wt, HH * G4 / 4);
    input_gemm<0><<<dim3(G4 / 128, MROWS / 128), 256>>>(seq1, Wt, xz, HH);
    trunc_kernel<<<(HH * G4 / 4 + 255) / 256, 256>>>(U2, Ut, HH * G4 / 4);
    lstm_rec<false><<<NBLK, NTHR>>>(xz, Ut, b2, nullptr);

    // ---- dense head ----
    dense_kernel<<<BB, OO>>>(Wd, bd, out);
}

// round 7
// speedup vs baseline: 3.7063x; 1.2009x over previous
#include <cuda_runtime.h>
#include <mma.h>
#include <math.h>

using namespace nvcuda;

#define BB 64
#define TT 256
#define DD 512
#define HH 1024
#define G4 4096
#define OO 512
#define NBLK 128
#define NTHR 256
#define MROWS (BB*TT)   // 16384

// dynamic smem layout for lstm_rec (floats):
//   Us : [1024][36]          -> 36864 floats (147456 B)
//   hs : [2][64][68]         ->  8704 floats ( 34816 B)
//   zs : [2][64][40]         ->  5120 floats ( 20480 B)
#define US_FLOATS  (1024 * 36)
#define HS_FLOATS  (2 * 64 * 68)
#define ZS_FLOATS  (2 * 64 * 40)
#define REC_SMEM_BYTES ((US_FLOATS + HS_FLOATS + ZS_FLOATS) * 4)   // 202752

// ---------------- scratch (device globals: allocation-free rule) -----------
__device__ float g_xz[(size_t)MROWS * G4];     // 256 MB
__device__ float g_seq1[(size_t)MROWS * HH];   // 64 MB, [t][b][h]
__device__ float g_Wt[(size_t)HH * G4];        // tf32-truncated W
__device__ float g_hA[BB * HH];
__device__ float g_hB[BB * HH];
__device__ unsigned g_count = 0;
__device__ volatile unsigned g_gen = 0;

__device__ __forceinline__ float to_tf32(float x) {
    float r; asm("cvt.rna.tf32.f32 %0, %1;" : "=f"(r) : "f"(x)); return r;
}

// ---------------- software grid barrier (all NBLK blocks resident) ---------
__device__ __forceinline__ void grid_barrier() {
    __syncthreads();
    if (threadIdx.x == 0) {
        __threadfence();
        unsigned gen = g_gen;
        if (atomicAdd(&g_count, 1u) == NBLK - 1u) {
            g_count = 0u;
            __threadfence();
            g_gen = gen + 1u;
        } else {
            while (g_gen == gen) __nanosleep(40);
        }
        __threadfence();
    }
    __syncthreads();
}

// ---------------- tf32 pre-truncation of weights (input GEMM B) ------------
__global__ void trunc_kernel(const float* __restrict__ in,
                             float* __restrict__ out, int n4)
{
    int i = blockIdx.x * blockDim.x + threadIdx.x;
    if (i < n4) {
        float4 v = ((const float4*)in)[i];
        v.x = to_tf32(v.x); v.y = to_tf32(v.y);
        v.z = to_tf32(v.z); v.w = to_tf32(v.w);
        ((float4*)out)[i] = v;
    }
}

// ---------------------------------------------------------------------------
// Input GEMM: C[r][n] = A[r][:] @ Bt[:][n]
// Block tile 128x128, BK=16, double-buffered smem, 8 warps (2x4),
// warp tile 64x32. REMAP=1: output row r=(t*64+b) <- x row (b*256+t).
// ---------------------------------------------------------------------------
template<int REMAP>
__global__ __launch_bounds__(256) void input_gemm(
    const float* __restrict__ A, const float* __restrict__ Bt,
    float* __restrict__ C, int K)
{
    __shared__ __align__(16) float As[2][128][20];
    __shared__ __align__(16) float Bs[2][16][136];
    const int tid = threadIdx.x;
    const int wid = tid >> 5;
    const int wr = wid >> 2;
    const int wc = wid & 3;
    const int r0 = blockIdx.y * 128, n0 = blockIdx.x * 128;

    wmma::fragment<wmma::accumulator, 16, 16, 8, float> c[4][2];
#pragma unroll
    for (int i = 0; i < 4; i++)
#pragma unroll
        for (int j = 0; j < 2; j++) wmma::fill_fragment(c[i][j], 0.f);

    const int arow = tid >> 1, ac8 = (tid & 1) * 8;
    const int rr = r0 + arow;
    const size_t gr = REMAP ? ((size_t)(rr & 63) * TT + (rr >> 6)) : (size_t)rr;
    const float* aptr = A + gr * K + ac8;
    const int brow = tid >> 4, bc8 = (tid & 15) * 8;
    const float* bptr = Bt + (size_t)brow * G4 + n0 + bc8;

    float4 a0, a1, b0, b1;

#define LOADK(kc)                                                   \
    do {                                                            \
        a0 = *(const float4*)(aptr + (kc));                         \
        a1 = *(const float4*)(aptr + (kc) + 4);                     \
        b0 = *(const float4*)(bptr + (size_t)(kc) * G4);            \
        b1 = *(const float4*)(bptr + (size_t)(kc) * G4 + 4);        \
    } while (0)

#define STOREK(s)                                                   \
    do {                                                            \
        As[s][arow][ac8 + 0] = to_tf32(a0.x);                       \
        As[s][arow][ac8 + 1] = to_tf32(a0.y);                       \
        As[s][arow][ac8 + 2] = to_tf32(a0.z);                       \
        As[s][arow][ac8 + 3] = to_tf32(a0.w);                       \
        As[s][arow][ac8 + 4] = to_tf32(a1.x);                       \
        As[s][arow][ac8 + 5] = to_tf32(a1.y);                       \
        As[s][arow][ac8 + 6] = to_tf32(a1.z);                       \
        As[s][arow][ac8 + 7] = to_tf32(a1.w);                       \
        *(float4*)&Bs[s][brow][bc8]     = b0;                       \
        *(float4*)&Bs[s][brow][bc8 + 4] = b1;                       \
    } while (0)

    LOADK(0);
    STOREK(0);
    __syncthreads();

    int s = 0;
    for (int kc = 0; kc < K; kc += 16) {
        const int nxt = kc + 16;
        if (nxt < K) LOADK(nxt);
#pragma unroll
        for (int kk = 0; kk < 2; kk++) {
            wmma::fragment<wmma::matrix_a, 16, 16, 8, wmma::precision::tf32, wmma::row_major> af[4];
            wmma::fragment<wmma::matrix_b, 16, 16, 8, wmma::precision::tf32, wmma::row_major> bf[2];
#pragma unroll
            for (int i = 0; i < 4; i++)
                wmma::load_matrix_sync(af[i], &As[s][wr * 64 + i * 16][kk * 8], 20);
#pragma unroll
            for (int j = 0; j < 2; j++)
                wmma::load_matrix_sync(bf[j], &Bs[s][kk * 8][wc * 32 + j * 16], 136);
#pragma unroll
            for (int i = 0; i < 4; i++)
#pragma unroll
                for (int j = 0; j < 2; j++)
                    wmma::mma_sync(c[i][j], af[i], bf[j], c[i][j]);
        }
        if (nxt < K) STOREK(s ^ 1);
        s ^= 1;
        __syncthreads();
    }
#undef LOADK
#undef STOREK

#pragma unroll
    for (int i = 0; i < 4; i++)
#pragma unroll
        for (int j = 0; j < 2; j++)
            wmma::store_matrix_sync(
                C + (size_t)(r0 + wr * 64 + i * 16) * G4 + n0 + wc * 32 + j * 16,
                c[i][j], G4, wmma::mem_row_major);
}

// ---------------------------------------------------------------------------
// Persistent recurrent layer v2.
//  - Entire U slice (1024 x 32, tf32) resident in smem for the whole layer.
//  - h chunks double-buffered: one __syncthreads per 64-k chunk; global
//    loads of chunk kc+1 issued before the MMAs of chunk kc.
//  - h stored pre-truncated to tf32 by the gate phase (staging = raw copies).
// ---------------------------------------------------------------------------
template<bool WRITE_SEQ>
__global__ __launch_bounds__(NTHR) void lstm_rec(
    const float* __restrict__ xz,   // [t*64+b][4096]
    const float* __restrict__ U,    // [1024][4096] raw fp32
    const float* __restrict__ bias, // [4096]
    float* __restrict__ seq_out)    // [t*64+b][1024] or null
{
    extern __shared__ __align__(16) float smem[];
    float* Us = smem;                               // [1024][36]
    float (*hs)[64][68] = (float(*)[64][68])(smem + US_FLOATS);
    float (*zs)[64][40] = (float(*)[64][40])(smem + US_FLOATS + HS_FLOATS);

    const int tid = threadIdx.x;
    const int wid = tid >> 5;
    const int wm = wid & 3;    // m-tile 0..3
    const int ks = wid >> 2;   // k-split 0..1
    const int u0 = blockIdx.x * 8;

    // ---- one-time: preload U slice (truncating to tf32) ------------------
    for (int i = tid; i < 1024 * 8; i += NTHR) {
        int krow = i >> 3, seg = i & 7;     // seg: 4 gates x 2 half-rows
        const float* p = U + (size_t)krow * G4 + (seg >> 1) * HH + u0 + (seg & 1) * 4;
        float4 v = *(const float4*)p;
        float* d = Us + krow * 36 + seg * 4;
        d[0] = to_tf32(v.x); d[1] = to_tf32(v.y);
        d[2] = to_tf32(v.z); d[3] = to_tf32(v.w);
    }

    float creg[2] = {0.f, 0.f};
    float bgs[2][4];
#pragma unroll
    for (int i = 0; i < 2; i++) {
        int p = tid + i * 256;
        int b = p >> 3, uu = p & 7;
        g_hA[b * HH + u0 + uu] = 0.f;
#pragma unroll
        for (int g = 0; g < 4; g++)
            bgs[i][g] = __ldg(&bias[g * HH + u0 + uu]);
    }
    grid_barrier();

    const int arow = tid >> 2, ak0 = (tid & 3) * 16;   // 64 rows x 64 k chunk

    for (int t = 0; t < TT; t++) {
        const float* hp = (t & 1) ? g_hB : g_hA;
        float*       hn = (t & 1) ? g_hA : g_hB;

        wmma::fragment<wmma::accumulator, 16, 16, 8, float> c0, c1;
        wmma::fill_fragment(c0, 0.f);
        wmma::fill_fragment(c1, 0.f);

        // prologue: chunk 0 -> regs -> hs[0]
        float4 av[4];
#pragma unroll
        for (int i = 0; i < 4; i++)
            av[i] = __ldcg((const float4*)(hp + (size_t)arow * HH + ak0) + i);
#pragma unroll
        for (int i = 0; i < 4; i++)
            *(float4*)&hs[0][arow][ak0 + i * 4] = av[i];
        __syncthreads();

        int s = 0;
#pragma unroll 4
        for (int kc = 0; kc < 16; kc++) {
            if (kc < 15) {
#pragma unroll
                for (int i = 0; i < 4; i++)
                    av[i] = __ldcg((const float4*)(hp + (size_t)arow * HH +
                                                   (kc + 1) * 64 + ak0) + i);
            }
#pragma unroll
            for (int j = 0; j < 4; j++) {
                int kk = ks * 4 + j;
                wmma::fragment<wmma::matrix_a, 16, 16, 8, wmma::precision::tf32, wmma::row_major> a;
                wmma::fragment<wmma::matrix_b, 16, 16, 8, wmma::precision::tf32, wmma::row_major> b0, b1;
                wmma::load_matrix_sync(a, &hs[s][wm * 16][kk * 8], 68);
                const float* ub = Us + (size_t)(kc * 64 + kk * 8) * 36;
                wmma::load_matrix_sync(b0, ub, 36);
                wmma::load_matrix_sync(b1, ub + 16, 36);
                wmma::mma_sync(c0, a, b0, c0);
                wmma::mma_sync(c1, a, b1, c1);
            }
            if (kc < 15) {
#pragma unroll
                for (int i = 0; i < 4; i++)
                    *(float4*)&hs[s ^ 1][arow][ak0 + i * 4] = av[i];
            }
            __syncthreads();
            s ^= 1;
        }

        wmma::store_matrix_sync(&zs[ks][wm * 16][0],  c0, 40, wmma::mem_row_major);
        wmma::store_matrix_sync(&zs[ks][wm * 16][16], c1, 40, wmma::mem_row_major);
        __syncthreads();

        // ---- fused gates -------------------------------------------------
#pragma unroll
        for (int i = 0; i < 2; i++) {
            int p = tid + i * 256;
            int b = p >> 3, uu = p & 7;
            const float* xzr = xz + ((size_t)t * BB + b) * G4;
            float zi = zs[0][b][0 * 8 + uu] + zs[1][b][0 * 8 + uu] + xzr[0 * HH + u0 + uu] + bgs[i][0];
            float zf = zs[0][b][1 * 8 + uu] + zs[1][b][1 * 8 + uu] + xzr[1 * HH + u0 + uu] + bgs[i][1];
            float zg = zs[0][b][2 * 8 + uu] + zs[1][b][2 * 8 + uu] + xzr[2 * HH + u0 + uu] + bgs[i][2];
            float zo = zs[0][b][3 * 8 + uu] + zs[1][b][3 * 8 + uu] + xzr[3 * HH + u0 + uu] + bgs[i][3];
            float ig = 1.f / (1.f + expf(-zi));
            float fg = 1.f / (1.f + expf(-zf));
            float og = 1.f / (1.f + expf(-zo));
            float cn = fg * creg[i] + ig * tanhf(zg);
            float hv = og * tanhf(cn);
            creg[i] = cn;
            hn[b * HH + u0 + uu] = to_tf32(hv);   // pre-truncated for next MMA
            if (WRITE_SEQ)
                seq_out[((size_t)t * BB + b) * HH + u0 + uu] = hv;
        }
        grid_barrier();
    }
}

// ---------------------------------------------------------------------------
// Final dense: out[b][o] = h_final[b][:] . Wd[:,o] + bd[o]  (h_final = g_hA)
// ---------------------------------------------------------------------------
__global__ __launch_bounds__(OO) void dense_kernel(
    const float* __restrict__ Wd, const float* __restrict__ bd,
    float* __restrict__ out)
{
    __shared__ float hs[HH];
    int b = blockIdx.x;
    int o = threadIdx.x;
    for (int k = o; k < HH; k += OO) hs[k] = g_hA[(size_t)b * HH + k];
    __syncthreads();
    float acc = 0.f;
#pragma unroll 8
    for (int k = 0; k < HH; k++)
        acc += hs[k] * __ldg(&Wd[(size_t)k * OO + o]);
    out[(size_t)b * OO + o] = acc + bd[o];
}

// ---------------------------------------------------------------------------
extern "C" void kernel_launch(void* const* d_in, const int* in_sizes, int n_in,
                              void* d_out, int out_size)
{
    const float* x  = (const float*)d_in[0];
    const float* W1 = (const float*)d_in[1];
    const float* U1 = (const float*)d_in[2];
    const float* b1 = (const float*)d_in[3];
    const float* W2 = (const float*)d_in[4];
    const float* U2 = (const float*)d_in[5];
    const float* b2 = (const float*)d_in[6];
    const float* Wd = (const float*)d_in[7];
    const float* bd = (const float*)d_in[8];
    float* out = (float*)d_out;

    float *xz, *seq1, *Wt;
    cudaGetSymbolAddress((void**)&xz,   g_xz);
    cudaGetSymbolAddress((void**)&seq1, g_seq1);
    cudaGetSymbolAddress((void**)&Wt,   g_Wt);

    cudaFuncSetAttribute(lstm_rec<true>,
        cudaFuncAttributeMaxDynamicSharedMemorySize, REC_SMEM_BYTES);
    cudaFuncSetAttribute(lstm_rec<false>,
        cudaFuncAttributeMaxDynamicSharedMemorySize, REC_SMEM_BYTES);

    // ---- layer 1 ----
    trunc_kernel<<<(DD * G4 / 4 + 255) / 256, 256>>>(W1, Wt, DD * G4 / 4);
    input_gemm<1><<<dim3(G4 / 128, MROWS / 128), 256>>>(x, Wt, xz, DD);
    lstm_rec<true><<<NBLK, NTHR, REC_SMEM_BYTES>>>(xz, U1, b1, seq1);

    // ---- layer 2 ----
    trunc_kernel<<<(HH * G4 / 4 + 255) / 256, 256>>>(W2, Wt, HH * G4 / 4);
    input_gemm<0><<<dim3(G4 / 128, MROWS / 128), 256>>>(seq1, Wt, xz, HH);
    lstm_rec<false><<<NBLK, NTHR, REC_SMEM_BYTES>>>(xz, U2, b2, nullptr);

    // ---- dense head ----
    dense_kernel<<<BB, OO>>>(Wd, bd, out);
}

// round 8
// speedup vs baseline: 4.7614x; 1.2847x over previous
#include <cuda_runtime.h>
#include <mma.h>
#include <math.h>

using namespace nvcuda;

#define BB 64
#define TT 256
#define DD 512
#define HH 1024
#define G4 4096
#define OO 512
#define NBLK 128
#define NTHR 256
#define REC_THR 512
#define MROWS (BB*TT)   // 16384

// dynamic smem layout for lstm_rec (floats):
//   Us : [1024][36]  -> 36864 floats (147456 B)
//   hs : [2][64][68] ->  8704 floats ( 34816 B)
//   zs : [4][64][40] -> 10240 floats ( 40960 B)
#define US_FLOATS  (1024 * 36)
#define HS_FLOATS  (2 * 64 * 68)
#define ZS_FLOATS  (4 * 64 * 40)
#define REC_SMEM_BYTES ((US_FLOATS + HS_FLOATS + ZS_FLOATS) * 4)   // 223232

// ---------------- scratch (device globals: allocation-free rule) -----------
__device__ float g_xz[(size_t)MROWS * G4];     // 256 MB
__device__ float g_seq1[(size_t)MROWS * HH];   // 64 MB, [t][b][h]
__device__ float g_Wt[(size_t)HH * G4];        // tf32-truncated W
__device__ float g_hA[BB * HH];
__device__ float g_hB[BB * HH];
__device__ unsigned g_count = 0;
__device__ volatile unsigned g_gen = 0;

__device__ __forceinline__ float to_tf32(float x) {
    float r; asm("cvt.rna.tf32.f32 %0, %1;" : "=f"(r) : "f"(x)); return r;
}

// ---------------- full software grid barrier (init only) -------------------
__device__ __forceinline__ void grid_barrier() {
    __syncthreads();
    if (threadIdx.x == 0) {
        __threadfence();
        unsigned gen = g_gen;
        if (atomicAdd(&g_count, 1u) == NBLK - 1u) {
            g_count = 0u;
            __threadfence();
            g_gen = gen + 1u;
        } else {
            while (g_gen == gen) {}
        }
        __threadfence();
    }
    __syncthreads();
}

// ---------------- tf32 pre-truncation of weights (input GEMM B) ------------
__global__ void trunc_kernel(const float* __restrict__ in,
                             float* __restrict__ out, int n4)
{
    int i = blockIdx.x * blockDim.x + threadIdx.x;
    if (i < n4) {
        float4 v = ((const float4*)in)[i];
        v.x = to_tf32(v.x); v.y = to_tf32(v.y);
        v.z = to_tf32(v.z); v.w = to_tf32(v.w);
        ((float4*)out)[i] = v;
    }
}

// ---------------------------------------------------------------------------
// Input GEMM: C[r][n] = A[r][:] @ Bt[:][n]   (frozen from round 5)
// ---------------------------------------------------------------------------
template<int REMAP>
__global__ __launch_bounds__(256) void input_gemm(
    const float* __restrict__ A, const float* __restrict__ Bt,
    float* __restrict__ C, int K)
{
    __shared__ __align__(16) float As[2][128][20];
    __shared__ __align__(16) float Bs[2][16][136];
    const int tid = threadIdx.x;
    const int wid = tid >> 5;
    const int wr = wid >> 2;
    const int wc = wid & 3;
    const int r0 = blockIdx.y * 128, n0 = blockIdx.x * 128;

    wmma::fragment<wmma::accumulator, 16, 16, 8, float> c[4][2];
#pragma unroll
    for (int i = 0; i < 4; i++)
#pragma unroll
        for (int j = 0; j < 2; j++) wmma::fill_fragment(c[i][j], 0.f);

    const int arow = tid >> 1, ac8 = (tid & 1) * 8;
    const int rr = r0 + arow;
    const size_t gr = REMAP ? ((size_t)(rr & 63) * TT + (rr >> 6)) : (size_t)rr;
    const float* aptr = A + gr * K + ac8;
    const int brow = tid >> 4, bc8 = (tid & 15) * 8;
    const float* bptr = Bt + (size_t)brow * G4 + n0 + bc8;

    float4 a0, a1, b0, b1;

#define LOADK(kc)                                                   \
    do {                                                            \
        a0 = *(const float4*)(aptr + (kc));                         \
        a1 = *(const float4*)(aptr + (kc) + 4);                     \
        b0 = *(const float4*)(bptr + (size_t)(kc) * G4);            \
        b1 = *(const float4*)(bptr + (size_t)(kc) * G4 + 4);        \
    } while (0)

#define STOREK(s)                                                   \
    do {                                                            \
        As[s][arow][ac8 + 0] = to_tf32(a0.x);                       \
        As[s][arow][ac8 + 1] = to_tf32(a0.y);                       \
        As[s][arow][ac8 + 2] = to_tf32(a0.z);                       \
        As[s][arow][ac8 + 3] = to_tf32(a0.w);                       \
        As[s][arow][ac8 + 4] = to_tf32(a1.x);                       \
        As[s][arow][ac8 + 5] = to_tf32(a1.y);                       \
        As[s][arow][ac8 + 6] = to_tf32(a1.z);                       \
        As[s][arow][ac8 + 7] = to_tf32(a1.w);                       \
        *(float4*)&Bs[s][brow][bc8]     = b0;                       \
        *(float4*)&Bs[s][brow][bc8 + 4] = b1;                       \
    } while (0)

    LOADK(0);
    STOREK(0);
    __syncthreads();

    int s = 0;
    for (int kc = 0; kc < K; kc += 16) {
        const int nxt = kc + 16;
        if (nxt < K) LOADK(nxt);
#pragma unroll
        for (int kk = 0; kk < 2; kk++) {
            wmma::fragment<wmma::matrix_a, 16, 16, 8, wmma::precision::tf32, wmma::row_major> af[4];
            wmma::fragment<wmma::matrix_b, 16, 16, 8, wmma::precision::tf32, wmma::row_major> bf[2];
#pragma unroll
            for (int i = 0; i < 4; i++)
                wmma::load_matrix_sync(af[i], &As[s][wr * 64 + i * 16][kk * 8], 20);
#pragma unroll
            for (int j = 0; j < 2; j++)
                wmma::load_matrix_sync(bf[j], &Bs[s][kk * 8][wc * 32 + j * 16], 136);
#pragma unroll
            for (int i = 0; i < 4; i++)
#pragma unroll
                for (int j = 0; j < 2; j++)
                    wmma::mma_sync(c[i][j], af[i], bf[j], c[i][j]);
        }
        if (nxt < K) STOREK(s ^ 1);
        s ^= 1;
        __syncthreads();
    }
#undef LOADK
#undef STOREK

#pragma unroll
    for (int i = 0; i < 4; i++)
#pragma unroll
        for (int j = 0; j < 2; j++)
            wmma::store_matrix_sync(
                C + (size_t)(r0 + wr * 64 + i * 16) * G4 + n0 + wc * 32 + j * 16,
                c[i][j], G4, wmma::mem_row_major);
}

// ---------------------------------------------------------------------------
// Persistent recurrent layer v3: 512 threads (16 warps: 4 m-tiles x 4 k-splits),
// U slice resident in smem, h double-buffered, xz prefetch overlapped with
// split-phase grid barrier.
// ---------------------------------------------------------------------------
template<bool WRITE_SEQ>
__global__ __launch_bounds__(REC_THR) void lstm_rec(
    const float* __restrict__ xz,   // [t*64+b][4096]
    const float* __restrict__ U,    // [1024][4096] raw fp32
    const float* __restrict__ bias, // [4096]
    float* __restrict__ seq_out)    // [t*64+b][1024] or null
{
    extern __shared__ __align__(16) float smem[];
    float* Us = smem;                               // [1024][36]
    float (*hs)[64][68] = (float(*)[64][68])(smem + US_FLOATS);
    float (*zs)[64][40] = (float(*)[64][40])(smem + US_FLOATS + HS_FLOATS);

    const int tid = threadIdx.x;
    const int wid = tid >> 5;
    const int wm = wid & 3;    // m-tile 0..3
    const int ks = wid >> 2;   // k-split 0..3
    const int u0 = blockIdx.x * 8;

    // ---- one-time: preload U slice (truncating to tf32) ------------------
    for (int i = tid; i < 1024 * 8; i += REC_THR) {
        int krow = i >> 3, seg = i & 7;
        const float* p = U + (size_t)krow * G4 + (seg >> 1) * HH + u0 + (seg & 1) * 4;
        float4 v = *(const float4*)p;
        float* d = Us + krow * 36 + seg * 4;
        d[0] = to_tf32(v.x); d[1] = to_tf32(v.y);
        d[2] = to_tf32(v.z); d[3] = to_tf32(v.w);
    }

    // gate mapping: one (b, unit) pair per thread
    const int gb = tid >> 3, gu = tid & 7;
    float creg = 0.f;
    float bg[4];
#pragma unroll
    for (int g = 0; g < 4; g++)
        bg[g] = __ldg(&bias[g * HH + u0 + gu]);
    g_hA[gb * HH + u0 + gu] = 0.f;

    // prefetch xz for t=0
    float xzv[4];
#pragma unroll
    for (int g = 0; g < 4; g++)
        xzv[g] = __ldcg(&xz[(size_t)gb * G4 + g * HH + u0 + gu]);

    grid_barrier();

    const int arow = tid >> 3, ak0 = (tid & 7) * 8;   // 64 rows x 64 k chunk

    for (int t = 0; t < TT; t++) {
        const float* hp = (t & 1) ? g_hB : g_hA;
        float*       hn = (t & 1) ? g_hA : g_hB;

        wmma::fragment<wmma::accumulator, 16, 16, 8, float> c0, c1;
        wmma::fill_fragment(c0, 0.f);
        wmma::fill_fragment(c1, 0.f);

        // prologue: chunk 0
        float4 av0 = __ldcg((const float4*)(hp + (size_t)arow * HH + ak0));
        float4 av1 = __ldcg((const float4*)(hp + (size_t)arow * HH + ak0 + 4));
        *(float4*)&hs[0][arow][ak0]     = av0;
        *(float4*)&hs[0][arow][ak0 + 4] = av1;
        __syncthreads();

        int s = 0;
#pragma unroll 4
        for (int kc = 0; kc < 16; kc++) {
            if (kc < 15) {
                const float* np = hp + (size_t)arow * HH + (kc + 1) * 64 + ak0;
                av0 = __ldcg((const float4*)np);
                av1 = __ldcg((const float4*)(np + 4));
            }
#pragma unroll
            for (int j = 0; j < 2; j++) {
                int kk = ks * 2 + j;
                wmma::fragment<wmma::matrix_a, 16, 16, 8, wmma::precision::tf32, wmma::row_major> a;
                wmma::fragment<wmma::matrix_b, 16, 16, 8, wmma::precision::tf32, wmma::row_major> b0, b1;
                wmma::load_matrix_sync(a, &hs[s][wm * 16][kk * 8], 68);
                const float* ub = Us + (size_t)(kc * 64 + kk * 8) * 36;
                wmma::load_matrix_sync(b0, ub, 36);
                wmma::load_matrix_sync(b1, ub + 16, 36);
                wmma::mma_sync(c0, a, b0, c0);
                wmma::mma_sync(c1, a, b1, c1);
            }
            if (kc < 15) {
                *(float4*)&hs[s ^ 1][arow][ak0]     = av0;
                *(float4*)&hs[s ^ 1][arow][ak0 + 4] = av1;
            }
            __syncthreads();
            s ^= 1;
        }

        wmma::store_matrix_sync(&zs[ks][wm * 16][0],  c0, 40, wmma::mem_row_major);
        wmma::store_matrix_sync(&zs[ks][wm * 16][16], c1, 40, wmma::mem_row_major);
        __syncthreads();

        // ---- fused gates (one pair per thread) ---------------------------
        {
            float z[4];
#pragma unroll
            for (int g = 0; g < 4; g++)
                z[g] = zs[0][gb][g * 8 + gu] + zs[1][gb][g * 8 + gu]
                     + zs[2][gb][g * 8 + gu] + zs[3][gb][g * 8 + gu]
                     + xzv[g] + bg[g];
            float ig = 1.f / (1.f + expf(-z[0]));
            float fg = 1.f / (1.f + expf(-z[1]));
            float og = 1.f / (1.f + expf(-z[3]));
            float cn = fg * creg + ig * tanhf(z[2]);
            float hv = og * tanhf(cn);
            creg = cn;
            hn[gb * HH + u0 + gu] = to_tf32(hv);
            if (WRITE_SEQ)
                seq_out[((size_t)t * BB + gb) * HH + u0 + gu] = hv;
        }
        __syncthreads();

        // ---- split-phase grid barrier with xz prefetch overlap -----------
        unsigned g0 = 0;
        if (tid == 0) {
            __threadfence();
            g0 = g_gen;
            if (atomicAdd(&g_count, 1u) == NBLK - 1u) {
                g_count = 0u;
                __threadfence();
                g_gen = g0 + 1u;
            }
        }
        if (t + 1 < TT) {
            const float* xzr = xz + ((size_t)(t + 1) * BB + gb) * G4;
#pragma unroll
            for (int g = 0; g < 4; g++)
                xzv[g] = __ldcg(&xzr[g * HH + u0 + gu]);
        }
        if (tid == 0) {
            while (g_gen == g0) {}
            __threadfence();
        }
        __syncthreads();
    }
}

// ---------------------------------------------------------------------------
// Final dense: out[b][o] = h_final[b][:] . Wd[:,o] + bd[o]  (h_final = g_hA)
// ---------------------------------------------------------------------------
__global__ __launch_bounds__(OO) void dense_kernel(
    const float* __restrict__ Wd, const float* __restrict__ bd,
    float* __restrict__ out)
{
    __shared__ float hs[HH];
    int b = blockIdx.x;
    int o = threadIdx.x;
    for (int k = o; k < HH; k += OO) hs[k] = g_hA[(size_t)b * HH + k];
    __syncthreads();
    float acc = 0.f;
#pragma unroll 8
    for (int k = 0; k < HH; k++)
        acc += hs[k] * __ldg(&Wd[(size_t)k * OO + o]);
    out[(size_t)b * OO + o] = acc + bd[o];
}

// ---------------------------------------------------------------------------
extern "C" void kernel_launch(void* const* d_in, const int* in_sizes, int n_in,
                              void* d_out, int out_size)
{
    const float* x  = (const float*)d_in[0];
    const float* W1 = (const float*)d_in[1];
    const float* U1 = (const float*)d_in[2];
    const float* b1 = (const float*)d_in[3];
    const float* W2 = (const float*)d_in[4];
    const float* U2 = (const float*)d_in[5];
    const float* b2 = (const float*)d_in[6];
    const float* Wd = (const float*)d_in[7];
    const float* bd = (const float*)d_in[8];
    float* out = (float*)d_out;

    float *xz, *seq1, *Wt;
    cudaGetSymbolAddress((void**)&xz,   g_xz);
    cudaGetSymbolAddress((void**)&seq1, g_seq1);
    cudaGetSymbolAddress((void**)&Wt,   g_Wt);

    cudaFuncSetAttribute(lstm_rec<true>,
        cudaFuncAttributeMaxDynamicSharedMemorySize, REC_SMEM_BYTES);
    cudaFuncSetAttribute(lstm_rec<false>,
        cudaFuncAttributeMaxDynamicSharedMemorySize, REC_SMEM_BYTES);

    // ---- layer 1 ----
    trunc_kernel<<<(DD * G4 / 4 + 255) / 256, 256>>>(W1, Wt, DD * G4 / 4);
    input_gemm<1><<<dim3(G4 / 128, MROWS / 128), 256>>>(x, Wt, xz, DD);
    lstm_rec<true><<<NBLK, REC_THR, REC_SMEM_BYTES>>>(xz, U1, b1, seq1);

    // ---- layer 2 ----
    trunc_kernel<<<(HH * G4 / 4 + 255) / 256, 256>>>(W2, Wt, HH * G4 / 4);
    input_gemm<0><<<dim3(G4 / 128, MROWS / 128), 256>>>(seq1, Wt, xz, HH);
    lstm_rec<false><<<NBLK, REC_THR, REC_SMEM_BYTES>>>(xz, U2, b2, nullptr);

    // ---- dense head ----
    dense_kernel<<<BB, OO>>>(Wd, bd, out);
}